// round 1
// baseline (speedup 1.0000x reference)
#include <cuda_runtime.h>

#define C_CH   128
#define HW     16384
#define BATCH  8
#define QKV_CH 384
#define NHEAD  8
#define DH     16
#define NCHUNK 16   // gram N-chunks per (b,head)

// ---------------- scratch (static device globals; no runtime allocation) ----
__device__ float g_qkv  [(long)BATCH * QKV_CH * HW];   // after 1x1 qkv conv
__device__ float g_qkv2 [(long)BATCH * QKV_CH * HW];   // after depthwise 3x3
__device__ float g_part [64 * NCHUNK * 288];           // gram partials + norm partials
__device__ float g_attn [64 * 256];                    // softmaxed 16x16 per (b,head)
__device__ float g_ctx  [(long)BATCH * C_CH * HW];     // attention output

// ---------------- SGEMM: C[z][m][n] = sum_k A[m][k] * B[z][k][n] -------------
// K = 128 fixed, N = 16384 fixed. M = gridDim.y * 128. fp32, 128x128x8 tiles,
// 8x8 per thread, 256 threads, register prefetch of next K-slab.
__global__ void __launch_bounds__(256) sgemm_k128(
    const float* __restrict__ A,    // [M,128] row-major
    const float* __restrict__ Bg,   // [batch][128][16384]
    float* __restrict__ Cg)         // [batch][M][16384]
{
    const int K = 128, N = HW;
    const float* B = Bg + (long)blockIdx.z * K * N;
    float*       C = Cg + (long)blockIdx.z * (long)gridDim.y * 128 * N;

    const int m0 = blockIdx.y * 128;
    const int n0 = blockIdx.x * 128;

    __shared__ float As[8][132];   // padded to kill STS/LDS conflicts
    __shared__ float Bs[8][128];

    const int tid = threadIdx.x;
    const int tx  = tid & 15;      // n-subtile
    const int ty  = tid >> 4;      // m-subtile

    // global load mapping
    const int arow = tid >> 1;          // 0..127 (m within tile)
    const int acol = (tid & 1) * 4;     // 0 or 4 (k within slab)
    const int brow = tid >> 5;          // 0..7   (k within slab)
    const int bcol = (tid & 31) * 4;    // 0..124 (n within tile)

    const float* Aptr = A + (long)(m0 + arow) * K + acol;
    const float* Bptr = B + (long)brow * N + n0 + bcol;

    float acc[8][8];
    #pragma unroll
    for (int i = 0; i < 8; i++)
        #pragma unroll
        for (int j = 0; j < 8; j++) acc[i][j] = 0.f;

    float4 av = *(const float4*)(Aptr);
    float4 bv = *(const float4*)(Bptr);

    for (int k0 = 0; k0 < K; k0 += 8) {
        As[acol + 0][arow] = av.x;
        As[acol + 1][arow] = av.y;
        As[acol + 2][arow] = av.z;
        As[acol + 3][arow] = av.w;
        *(float4*)&Bs[brow][bcol] = bv;
        __syncthreads();

        if (k0 + 8 < K) {
            av = *(const float4*)(Aptr + k0 + 8);
            bv = *(const float4*)(Bptr + (long)(k0 + 8) * N);
        }

        #pragma unroll
        for (int kk = 0; kk < 8; kk++) {
            float a[8], b[8];
            #pragma unroll
            for (int u = 0; u < 8; u++) a[u] = As[kk][ty * 8 + u];
            #pragma unroll
            for (int u = 0; u < 8; u++) b[u] = Bs[kk][tx * 8 + u];
            #pragma unroll
            for (int i = 0; i < 8; i++)
                #pragma unroll
                for (int j = 0; j < 8; j++)
                    acc[i][j] += a[i] * b[j];
        }
        __syncthreads();
    }

    #pragma unroll
    for (int i = 0; i < 8; i++) {
        float* crow = C + (long)(m0 + ty * 8 + i) * N + n0 + tx * 8;
        *(float4*)(crow)     = make_float4(acc[i][0], acc[i][1], acc[i][2], acc[i][3]);
        *(float4*)(crow + 4) = make_float4(acc[i][4], acc[i][5], acc[i][6], acc[i][7]);
    }
}

// ---------------- depthwise 3x3, SAME padding, per-channel weights ----------
__global__ void __launch_bounds__(256) dwconv3x3(
    const float* __restrict__ in,   // [B*384][128][128]
    const float* __restrict__ w,    // [384][1][3][3]
    float* __restrict__ out)
{
    const int n  = blockIdx.x * 256 + threadIdx.x;   // 0..16383
    const int bc = blockIdx.y;                        // 0..3071
    const int ch = bc % QKV_CH;
    const int y  = n >> 7;
    const int x  = n & 127;

    const float* ip = in + (long)bc * HW;
    const float* wp = w + ch * 9;

    float s = 0.f;
    #pragma unroll
    for (int dy = -1; dy <= 1; dy++) {
        const int yy = y + dy;
        if (yy < 0 || yy > 127) continue;
        #pragma unroll
        for (int dx = -1; dx <= 1; dx++) {
            const int xx = x + dx;
            if (xx < 0 || xx > 127) continue;
            s += ip[yy * 128 + xx] * wp[(dy + 1) * 3 + (dx + 1)];
        }
    }
    out[(long)bc * HW + n] = s;
}

// ---------------- gram partials: S[i][j] = sum_n q[i][n]k[j][n], + norms ----
// grid (NCHUNK, 64). Each block: one (b,head), one 1024-wide N chunk.
__global__ void __launch_bounds__(256) gram16(
    const float* __restrict__ qkv2, float* __restrict__ partials)
{
    const int bh = blockIdx.y;
    const int b  = bh >> 3, hd = bh & 7;
    const int n0 = blockIdx.x * 1024;

    const float* qg = qkv2 + (long)b * QKV_CH * HW + (long)hd * DH * HW + n0;
    const float* kg = qg + (long)C_CH * HW;

    __shared__ float qs[16 * 129];
    __shared__ float ks[16 * 129];

    const int tid = threadIdx.x;
    const int i = tid >> 4, j = tid & 15;

    float acc = 0.f, nacc = 0.f;

    for (int t0 = 0; t0 < 1024; t0 += 128) {
        #pragma unroll
        for (int idx = tid; idx < 2048; idx += 256) {
            const int r = idx >> 7, c = idx & 127;
            qs[r * 129 + c] = qg[(long)r * HW + t0 + c];
            ks[r * 129 + c] = kg[(long)r * HW + t0 + c];
        }
        __syncthreads();
        #pragma unroll 8
        for (int t = 0; t < 128; t++)
            acc += qs[i * 129 + t] * ks[j * 129 + t];
        if (tid < 16) {
            #pragma unroll 8
            for (int t = 0; t < 128; t++) { float v = qs[tid * 129 + t]; nacc += v * v; }
        } else if (tid < 32) {
            #pragma unroll 8
            for (int t = 0; t < 128; t++) { float v = ks[(tid - 16) * 129 + t]; nacc += v * v; }
        }
        __syncthreads();
    }

    float* p = partials + ((long)bh * NCHUNK + blockIdx.x) * 288;
    p[tid] = acc;
    if (tid < 32) p[256 + tid] = nacc;
}

// ---------------- reduce partials + normalize + temperature + softmax -------
__global__ void __launch_bounds__(256) attn_softmax(
    const float* __restrict__ partials,
    const float* __restrict__ temperature,
    float* __restrict__ attn)
{
    const int bh = blockIdx.x;
    const int hd = bh & 7;
    __shared__ float S[256];
    __shared__ float qn[16], kn[16];

    const int tid = threadIdx.x;
    float s = 0.f;
    #pragma unroll
    for (int c = 0; c < NCHUNK; c++)
        s += partials[((long)bh * NCHUNK + c) * 288 + tid];
    S[tid] = s;

    if (tid < 32) {
        float ns = 0.f;
        #pragma unroll
        for (int c = 0; c < NCHUNK; c++)
            ns += partials[((long)bh * NCHUNK + c) * 288 + 256 + tid];
        const float nv = fmaxf(sqrtf(ns), 1e-12f);
        if (tid < 16) qn[tid] = nv; else kn[tid - 16] = nv;
    }
    __syncthreads();

    if (tid < 16) {
        const int   i  = tid;
        const float tp = temperature[hd];
        float lg[16];
        float mx = -1e30f;
        #pragma unroll
        for (int j = 0; j < 16; j++) {
            lg[j] = S[i * 16 + j] / (qn[i] * kn[j]) * tp;
            mx = fmaxf(mx, lg[j]);
        }
        float sum = 0.f;
        #pragma unroll
        for (int j = 0; j < 16; j++) { lg[j] = expf(lg[j] - mx); sum += lg[j]; }
        const float inv = 1.f / sum;
        #pragma unroll
        for (int j = 0; j < 16; j++)
            attn[(long)bh * 256 + i * 16 + j] = lg[j] * inv;
    }
}

// ---------------- ctx[i][n] = sum_j attn[i][j] * v[j][n] * illu[j][n] -------
__global__ void __launch_bounds__(256) attn_apply(
    const float* __restrict__ qkv2,
    const float* __restrict__ illu,
    const float* __restrict__ attn,
    float* __restrict__ ctx)
{
    const int bh = blockIdx.y;
    const int b  = bh >> 3, hd = bh & 7;

    __shared__ float a[256];
    a[threadIdx.x] = attn[(long)bh * 256 + threadIdx.x];
    __syncthreads();

    const int n = blockIdx.x * 256 + threadIdx.x;
    const float* v  = qkv2 + (long)b * QKV_CH * HW + (long)(2 * C_CH + hd * DH) * HW + n;
    const float* il = illu + (long)b * C_CH   * HW + (long)(hd * DH) * HW + n;

    float vv[16];
    #pragma unroll
    for (int j = 0; j < 16; j++)
        vv[j] = v[(long)j * HW] * il[(long)j * HW];

    float* o = ctx + (long)b * C_CH * HW + (long)(hd * DH) * HW + n;
    #pragma unroll
    for (int i = 0; i < 16; i++) {
        float s = 0.f;
        #pragma unroll
        for (int j = 0; j < 16; j++)
            s += a[i * 16 + j] * vv[j];
        o[(long)i * HW] = s;
    }
}

// ---------------- launch --------------------------------------------------
extern "C" void kernel_launch(void* const* d_in, const int* in_sizes, int n_in,
                              void* d_out, int out_size)
{
    const float* x_in   = (const float*)d_in[0];
    const float* illu   = (const float*)d_in[1];
    const float* w_qkv  = (const float*)d_in[2];
    const float* w_dw   = (const float*)d_in[3];
    const float* w_proj = (const float*)d_in[4];
    const float* temp   = (const float*)d_in[5];
    float* out = (float*)d_out;

    float *qkv, *qkv2, *part, *attn, *ctx;
    cudaGetSymbolAddress((void**)&qkv,  g_qkv);
    cudaGetSymbolAddress((void**)&qkv2, g_qkv2);
    cudaGetSymbolAddress((void**)&part, g_part);
    cudaGetSymbolAddress((void**)&attn, g_attn);
    cudaGetSymbolAddress((void**)&ctx,  g_ctx);

    // 1) qkv = w_qkv @ x   (per batch: M=384, K=128, N=16384)
    sgemm_k128<<<dim3(HW / 128, QKV_CH / 128, BATCH), 256>>>(w_qkv, x_in, qkv);
    // 2) depthwise 3x3 SAME
    dwconv3x3<<<dim3(HW / 256, BATCH * QKV_CH), 256>>>(qkv, w_dw, qkv2);
    // 3) gram partials + norms
    gram16<<<dim3(NCHUNK, 64), 256>>>(qkv2, part);
    // 4) softmax(16x16) with l2-normalization and temperature
    attn_softmax<<<64, 256>>>(part, temp, attn);
    // 5) out = attn @ (v * illu)
    attn_apply<<<dim3(HW / 256, 64), 256>>>(qkv2, illu, attn, ctx);
    // 6) project_out (per batch: M=128, K=128, N=16384)
    sgemm_k128<<<dim3(HW / 128, C_CH / 128, BATCH), 256>>>(w_proj, ctx, out);
}